// round 9
// baseline (speedup 1.0000x reference)
#include <cuda_runtime.h>
#include <cuda_fp16.h>
#include <cstdint>

#define B_   16
#define IC_  128
#define OC_  128
#define SD_  512
#define H_   128
#define W_   128
#define HW_  (H_*W_)   // 16384

#define CONV_SCALE 0.029462782549439476f   // 1/sqrt(1152)
#define LIN_SCALE  0.044194173824159216f   // 1/sqrt(512)

// ---------------- device scratch (no allocation allowed) -------------------
__device__ float  g_s[B_ * IC_];                          // modulation s[b][ic]
__device__ __half g_wh[(size_t)B_ * 9 * OC_ * IC_];       // [b][tap][oc][ic] fp16
__device__ __half g_ch[(size_t)B_ * HW_ * IC_];           // [b][pixel][ic] fp16 channels-last

// ---------------- helpers ---------------------------------------------------
__device__ __forceinline__ uint32_t s2u(const void* p) {
    uint32_t a;
    asm("{ .reg .u64 t; cvta.to.shared.u64 t, %1; cvt.u32.u64 %0, t; }" : "=r"(a) : "l"(p));
    return a;
}
__device__ __forceinline__ void cpa16(uint32_t dst, const void* src, int sz) {
    asm volatile("cp.async.cg.shared.global [%0], [%1], 16, %2;"
                 :: "r"(dst), "l"(src), "r"(sz) : "memory");
}
__device__ __forceinline__ void ldsm_x4(uint32_t a, uint32_t& r0, uint32_t& r1,
                                        uint32_t& r2, uint32_t& r3) {
    asm volatile("ldmatrix.sync.aligned.m8n8.x4.shared.b16 {%0,%1,%2,%3}, [%4];"
                 : "=r"(r0), "=r"(r1), "=r"(r2), "=r"(r3) : "r"(a));
}
__device__ __forceinline__ void hmma(float& c0, float& c1, float& c2, float& c3,
                                     uint32_t a0, uint32_t a1, uint32_t a2, uint32_t a3,
                                     uint32_t b0, uint32_t b1) {
    asm volatile(
        "mma.sync.aligned.m16n8k16.row.col.f32.f16.f16.f32 "
        "{%0,%1,%2,%3}, {%4,%5,%6,%7}, {%8,%9}, {%0,%1,%2,%3};"
        : "+f"(c0), "+f"(c1), "+f"(c2), "+f"(c3)
        : "r"(a0), "r"(a1), "r"(a2), "r"(a3), "r"(b0), "r"(b1));
}

// ---------------------------------------------------------------------------
// Kernel 1: s[b][ic] = dot(style[b], mod_w[ic]) * lin_scale + mod_b[ic]
// ---------------------------------------------------------------------------
__global__ void mod_kernel(const float* __restrict__ style,
                           const float* __restrict__ mod_w,
                           const float* __restrict__ mod_b) {
    int warp = threadIdx.x >> 5, lane = threadIdx.x & 31;
    int idx  = blockIdx.x * 4 + warp;
    int b = idx >> 7, ic = idx & 127;
    const float* st = style + b * SD_;
    const float* mw = mod_w + ic * SD_;
    float sum = 0.f;
    #pragma unroll 4
    for (int j = lane; j < SD_; j += 32) sum += st[j] * mw[j];
    #pragma unroll
    for (int o = 16; o; o >>= 1) sum += __shfl_xor_sync(0xffffffffu, sum, o);
    if (lane == 0) g_s[idx] = sum * LIN_SCALE + mod_b[ic];
}

// ---------------------------------------------------------------------------
// Kernel 2: demodulate, write fp16 weights g_wh[b][tap][oc][ic]
// ---------------------------------------------------------------------------
__global__ void demod_kernel(const float* __restrict__ weight) {
    int oc = blockIdx.x, b = blockIdx.y, ic = threadIdx.x;
    float s = g_s[b * IC_ + ic];
    const float* wp = weight + ((size_t)oc * IC_ + ic) * 9;
    float v[9], ss = 0.f;
    #pragma unroll
    for (int k = 0; k < 9; ++k) { v[k] = CONV_SCALE * wp[k] * s; ss += v[k] * v[k]; }
    #pragma unroll
    for (int o = 16; o; o >>= 1) ss += __shfl_xor_sync(0xffffffffu, ss, o);
    __shared__ float red[4];
    if ((threadIdx.x & 31) == 0) red[threadIdx.x >> 5] = ss;
    __syncthreads();
    float demod = rsqrtf(red[0] + red[1] + red[2] + red[3] + 1e-8f);
    #pragma unroll
    for (int k = 0; k < 9; ++k)
        g_wh[((size_t)(b * 9 + k) * OC_ + oc) * IC_ + ic] = __float2half(v[k] * demod);
}

// ---------------------------------------------------------------------------
// Kernel 3: content -> fp16 channels-last: g_ch[b][y*W+x][ic] = content[b][ic][y][x]
// ---------------------------------------------------------------------------
__global__ void prep_content(const float* __restrict__ content) {
    __shared__ __half sm[128][130];          // 260B rows: odd 4B stride, conflict-free
    int y = blockIdx.x, b = blockIdx.y, tid = threadIdx.x;
    const float* src = content + (size_t)b * IC_ * HW_ + y * W_;
    for (int i = tid; i < IC_ * W_; i += 256) {
        int ic = i >> 7, x = i & 127;
        sm[x][ic] = __float2half(src[(size_t)ic * HW_ + x]);
    }
    __syncthreads();
    uint32_t* dst = (uint32_t*)(g_ch + ((size_t)b * HW_ + (size_t)y * W_) * IC_);
    for (int i = tid; i < IC_ * W_ / 2; i += 256) {
        int x = i >> 6, icp = i & 63;
        __half2 h = __halves2half2(sm[x][2 * icp], sm[x][2 * icp + 1]);
        dst[(size_t)x * (IC_ / 2) + icp] = *reinterpret_cast<uint32_t*>(&h);
    }
}

// ---------------------------------------------------------------------------
// Kernel 4: implicit GEMM conv (HMMA). CTA = row-pair (2 rows) of one sample:
// D[128 oc][256 px], K = 9 taps x 128 ic. 8 warps as 2(M) x 4(N); warp tile
// 64 oc x 64 px -> HMMA:LDSM.x4 = 4.0. 18 stages (tap x ic-chunk 64):
// A[128 oc][64 ic] 16KB + B[256 px][64 ic] 32KB, double-buffered (96KB),
// single __syncthreads per stage.
// ---------------------------------------------------------------------------
#define NST 18
#define STG 49152                     // A(16384) + B(32768)
#define SM_TOTAL (2 * STG)

__global__ void __launch_bounds__(256) conv_mma(float* __restrict__ out) {
    extern __shared__ char smem[];
    const uint32_t sb = s2u(smem);
    const int tid = threadIdx.x, wid = tid >> 5, lane = tid & 31;
    const int y0 = blockIdx.x * 2, b = blockIdx.y;
    const int warp_m = wid & 1, warp_n = wid >> 1;

    float acc[4][8][4];
    #pragma unroll
    for (int mt = 0; mt < 4; ++mt)
        #pragma unroll
        for (int nt = 0; nt < 8; ++nt)
            #pragma unroll
            for (int c = 0; c < 4; ++c) acc[mt][nt][c] = 0.f;

    // ---- stage loader ----
    auto issue = [&](int s) {
        const uint32_t base = sb + (uint32_t)(s & 1) * STG;
        const int tap = s % 9, chunk = s / 9;
        const int dy = tap / 3 - 1, dx = tap % 3;
        // A: weights [128 oc][64 ic], 4 x 16B per thread
        const char* asrc = (const char*)g_wh
            + ((size_t)(b * 9 + tap) * OC_ * IC_ + chunk * 64) * 2;
        #pragma unroll
        for (int j = 0; j < 4; ++j) {
            int i = tid + j * 256;               // 0..1023
            int row = i >> 3, c16 = i & 7;
            uint32_t off = (uint32_t)(row * 128 + c16 * 16);
            cpa16(base + (off ^ (((uint32_t)row & 7u) << 4)),
                  asrc + (size_t)row * IC_ * 2 + c16 * 16, 16);
        }
        // B: content [256 px][64 ic]; px = r*128 + x, src row y0+r+dy, col x+dx-1
        #pragma unroll
        for (int j = 0; j < 8; ++j) {
            int i = tid + j * 256;               // 0..2047
            int row = i >> 3, c16 = i & 7;       // row = px
            int r = row >> 7, x = row & 127;
            int gy = y0 + r + dy;
            int xs = x + dx - 1;
            int ok = (gy >= 0 && gy < H_ && xs >= 0 && xs < W_) ? 16 : 0;
            size_t pix = (size_t)(ok ? gy : 0) * W_ + (ok ? xs : 0);
            uint32_t off = (uint32_t)(row * 128 + c16 * 16);
            cpa16(base + 16384u + (off ^ (((uint32_t)row & 7u) << 4)),
                  (const char*)(g_ch + ((size_t)b * HW_ + pix) * IC_ + chunk * 64)
                      + c16 * 16, ok);
        }
        asm volatile("cp.async.commit_group;" ::: "memory");
    };

    issue(0);

    #pragma unroll 1
    for (int s = 0; s < NST; ++s) {
        asm volatile("cp.async.wait_group 0;" ::: "memory");
        __syncthreads();
        if (s + 1 < NST) issue(s + 1);           // overlaps compute(s)
        const uint32_t Abase = sb + (uint32_t)(s & 1) * STG;
        const uint32_t Bbase = Abase + 16384u;

        #pragma unroll
        for (int kst = 0; kst < 4; ++kst) {
            uint32_t a[4][4];
            #pragma unroll
            for (int mt = 0; mt < 4; ++mt) {
                int row = warp_m * 64 + mt * 16 + (lane & 15);
                int kc  = kst * 2 + (lane >> 4);
                uint32_t off = (uint32_t)(row * 128 + kc * 16);
                ldsm_x4(Abase + (off ^ (((uint32_t)row & 7u) << 4)),
                        a[mt][0], a[mt][1], a[mt][2], a[mt][3]);
            }
            uint32_t bf[8][2];
            #pragma unroll
            for (int ntp = 0; ntp < 4; ++ntp) {
                int n  = warp_n * 64 + ntp * 16 + ((lane >> 4) << 3) + (lane & 7);
                int kc = kst * 2 + ((lane >> 3) & 1);
                uint32_t off = (uint32_t)(n * 128 + kc * 16);
                ldsm_x4(Bbase + (off ^ (((uint32_t)n & 7u) << 4)),
                        bf[2 * ntp][0], bf[2 * ntp][1],
                        bf[2 * ntp + 1][0], bf[2 * ntp + 1][1]);
            }
            #pragma unroll
            for (int mt = 0; mt < 4; ++mt)
                #pragma unroll
                for (int nt = 0; nt < 8; ++nt)
                    hmma(acc[mt][nt][0], acc[mt][nt][1], acc[mt][nt][2], acc[mt][nt][3],
                         a[mt][0], a[mt][1], a[mt][2], a[mt][3],
                         bf[nt][0], bf[nt][1]);
        }
    }

    // ---- epilogue ----
    const int qm = lane >> 2, qn = (lane & 3) * 2;
    #pragma unroll
    for (int mt = 0; mt < 4; ++mt) {
        #pragma unroll
        for (int nt = 0; nt < 8; ++nt) {
            int oc0 = warp_m * 64 + mt * 16 + qm;
            int px  = warp_n * 64 + nt * 8 + qn;      // 0..255
            int yy  = y0 + (px >> 7), x = px & 127;
            float* d0 = out + ((size_t)(b * OC_ + oc0)) * HW_ + (size_t)yy * W_ + x;
            *reinterpret_cast<float2*>(d0) =
                make_float2(acc[mt][nt][0], acc[mt][nt][1]);
            *reinterpret_cast<float2*>(d0 + 8 * HW_) =
                make_float2(acc[mt][nt][2], acc[mt][nt][3]);
        }
    }
}

// ---------------------------------------------------------------------------
extern "C" void kernel_launch(void* const* d_in, const int* in_sizes, int n_in,
                              void* d_out, int out_size) {
    const float* content = (const float*)d_in[0];
    const float* style   = (const float*)d_in[1];
    const float* weight  = (const float*)d_in[2];
    const float* mod_w   = (const float*)d_in[3];
    const float* mod_b   = (const float*)d_in[4];
    float* out = (float*)d_out;

    cudaFuncSetAttribute(conv_mma, cudaFuncAttributeMaxDynamicSharedMemorySize, SM_TOTAL);

    mod_kernel<<<512, 128>>>(style, mod_w, mod_b);
    demod_kernel<<<dim3(OC_, B_), 128>>>(weight);
    prep_content<<<dim3(H_, B_), 256>>>(content);
    conv_mma<<<dim3(H_ / 2, B_), 256, SM_TOTAL>>>(out);
}

// round 10
// speedup vs baseline: 1.1856x; 1.1856x over previous
#include <cuda_runtime.h>
#include <cuda_fp16.h>
#include <cstdint>

#define B_   16
#define IC_  128
#define OC_  128
#define SD_  512
#define H_   128
#define W_   128
#define HW_  (H_*W_)   // 16384

#define CONV_SCALE 0.029462782549439476f   // 1/sqrt(1152)
#define LIN_SCALE  0.044194173824159216f   // 1/sqrt(512)

// ---------------- device scratch (no allocation allowed) -------------------
__device__ float  g_s[B_ * IC_];                          // modulation s[b][ic]
__device__ __half g_wh[(size_t)B_ * 9 * OC_ * IC_];       // [b][tap][oc][ic] fp16
__device__ __half g_ch[(size_t)B_ * HW_ * IC_];           // [b][pixel][ic] fp16 channels-last

// ---------------- helpers ---------------------------------------------------
__device__ __forceinline__ uint32_t s2u(const void* p) {
    uint32_t a;
    asm("{ .reg .u64 t; cvta.to.shared.u64 t, %1; cvt.u32.u64 %0, t; }" : "=r"(a) : "l"(p));
    return a;
}
__device__ __forceinline__ void cpa16(uint32_t dst, const void* src, int sz) {
    asm volatile("cp.async.cg.shared.global [%0], [%1], 16, %2;"
                 :: "r"(dst), "l"(src), "r"(sz) : "memory");
}
__device__ __forceinline__ void ldsm_x4(uint32_t a, uint32_t& r0, uint32_t& r1,
                                        uint32_t& r2, uint32_t& r3) {
    asm volatile("ldmatrix.sync.aligned.m8n8.x4.shared.b16 {%0,%1,%2,%3}, [%4];"
                 : "=r"(r0), "=r"(r1), "=r"(r2), "=r"(r3) : "r"(a));
}
__device__ __forceinline__ void hmma(float& c0, float& c1, float& c2, float& c3,
                                     uint32_t a0, uint32_t a1, uint32_t a2, uint32_t a3,
                                     uint32_t b0, uint32_t b1) {
    asm volatile(
        "mma.sync.aligned.m16n8k16.row.col.f32.f16.f16.f32 "
        "{%0,%1,%2,%3}, {%4,%5,%6,%7}, {%8,%9}, {%0,%1,%2,%3};"
        : "+f"(c0), "+f"(c1), "+f"(c2), "+f"(c3)
        : "r"(a0), "r"(a1), "r"(a2), "r"(a3), "r"(b0), "r"(b1));
}

// ---------------------------------------------------------------------------
// Kernel 1: s[b][ic] = dot(style[b], mod_w[ic]) * lin_scale + mod_b[ic]
// ---------------------------------------------------------------------------
__global__ void mod_kernel(const float* __restrict__ style,
                           const float* __restrict__ mod_w,
                           const float* __restrict__ mod_b) {
    int warp = threadIdx.x >> 5, lane = threadIdx.x & 31;
    int idx  = blockIdx.x * 4 + warp;
    int b = idx >> 7, ic = idx & 127;
    const float* st = style + b * SD_;
    const float* mw = mod_w + ic * SD_;
    float sum = 0.f;
    #pragma unroll 4
    for (int j = lane; j < SD_; j += 32) sum += st[j] * mw[j];
    #pragma unroll
    for (int o = 16; o; o >>= 1) sum += __shfl_xor_sync(0xffffffffu, sum, o);
    if (lane == 0) g_s[idx] = sum * LIN_SCALE + mod_b[ic];
}

// ---------------------------------------------------------------------------
// Kernel 2: demodulate, write fp16 weights g_wh[b][tap][oc][ic]
// ---------------------------------------------------------------------------
__global__ void demod_kernel(const float* __restrict__ weight) {
    int oc = blockIdx.x, b = blockIdx.y, ic = threadIdx.x;
    float s = g_s[b * IC_ + ic];
    const float* wp = weight + ((size_t)oc * IC_ + ic) * 9;
    float v[9], ss = 0.f;
    #pragma unroll
    for (int k = 0; k < 9; ++k) { v[k] = CONV_SCALE * wp[k] * s; ss += v[k] * v[k]; }
    #pragma unroll
    for (int o = 16; o; o >>= 1) ss += __shfl_xor_sync(0xffffffffu, ss, o);
    __shared__ float red[4];
    if ((threadIdx.x & 31) == 0) red[threadIdx.x >> 5] = ss;
    __syncthreads();
    float demod = rsqrtf(red[0] + red[1] + red[2] + red[3] + 1e-8f);
    #pragma unroll
    for (int k = 0; k < 9; ++k)
        g_wh[((size_t)(b * 9 + k) * OC_ + oc) * IC_ + ic] = __float2half(v[k] * demod);
}

// ---------------------------------------------------------------------------
// Kernel 3: content -> fp16 channels-last: g_ch[b][y*W+x][ic] = content[b][ic][y][x]
// ---------------------------------------------------------------------------
__global__ void prep_content(const float* __restrict__ content) {
    __shared__ __half sm[128][130];
    int y = blockIdx.x, b = blockIdx.y, tid = threadIdx.x;
    const float* src = content + (size_t)b * IC_ * HW_ + y * W_;
    for (int i = tid; i < IC_ * W_; i += 256) {
        int ic = i >> 7, x = i & 127;
        sm[x][ic] = __float2half(src[(size_t)ic * HW_ + x]);
    }
    __syncthreads();
    uint32_t* dst = (uint32_t*)(g_ch + ((size_t)b * HW_ + (size_t)y * W_) * IC_);
    for (int i = tid; i < IC_ * W_ / 2; i += 256) {
        int x = i >> 6, icp = i & 63;
        __half2 h = __halves2half2(sm[x][2 * icp], sm[x][2 * icp + 1]);
        dst[(size_t)x * (IC_ / 2) + icp] = *reinterpret_cast<uint32_t*>(&h);
    }
}

// ---------------------------------------------------------------------------
// Kernel 4: implicit GEMM conv (HMMA). CTA = (row y, sample b): D[128 oc][128 px],
// K = 9 taps x 128 ic. 8 warps: warp_m = wid&3 (32 oc), warp_n = wid>>2 (64 px).
// 18 stages (tap x ic-chunk 64): A[128][64] 16KB + B[128][64] 16KB per stage.
// THREE-buffer cp.async ring, ONE __syncthreads per stage, forced 2 CTAs/SM.
// ---------------------------------------------------------------------------
#define NST 18
#define STG 32768                      // A(16KB) + B(16KB)
#define SM_TOTAL (3 * STG)             // 96KB -> 2 CTAs/SM (192KB)

__global__ void __launch_bounds__(256, 2) conv_mma(float* __restrict__ out) {
    extern __shared__ char smem[];
    const uint32_t sb = s2u(smem);
    const int tid = threadIdx.x, wid = tid >> 5, lane = tid & 31;
    const int y = blockIdx.x, b = blockIdx.y;
    const int warp_m = wid & 3, warp_n = wid >> 2;

    float acc[2][8][4];
    #pragma unroll
    for (int mt = 0; mt < 2; ++mt)
        #pragma unroll
        for (int nt = 0; nt < 8; ++nt)
            #pragma unroll
            for (int c = 0; c < 4; ++c) acc[mt][nt][c] = 0.f;

    // ---- stage loader into explicit buffer base ----
    auto issue = [&](int s, uint32_t base) {
        const int tap = s % 9, chunk = s / 9;
        const int dy = tap / 3 - 1, dx = tap % 3;
        const char* asrc = (const char*)g_wh
            + ((size_t)(b * 9 + tap) * OC_ * IC_ + chunk * 64) * 2;
        #pragma unroll
        for (int j = 0; j < 4; ++j) {
            int i = tid + j * 256;               // 0..1023
            int row = i >> 3, c16 = i & 7;
            uint32_t off = (uint32_t)(row * 128 + c16 * 16);
            cpa16(base + (off ^ (((uint32_t)row & 7u) << 4)),
                  asrc + (size_t)row * IC_ * 2 + c16 * 16, 16);
        }
        const int yy = y + dy;
        const int rowok = (yy >= 0 && yy < H_);
        const __half* brow = g_ch + ((size_t)b * HW_ + (size_t)(rowok ? yy : 0) * W_) * IC_;
        #pragma unroll
        for (int j = 0; j < 4; ++j) {
            int i = tid + j * 256;
            int row = i >> 3, c16 = i & 7;       // row = x coordinate
            int xs = row + dx - 1;
            int ok = (rowok && xs >= 0 && xs < W_) ? 16 : 0;
            int xc = (xs >= 0 && xs < W_) ? xs : 0;
            uint32_t off = (uint32_t)(row * 128 + c16 * 16);
            cpa16(base + 16384u + (off ^ (((uint32_t)row & 7u) << 4)),
                  (const char*)(brow + (size_t)xc * IC_ + chunk * 64) + c16 * 16, ok);
        }
        asm volatile("cp.async.commit_group;" ::: "memory");
    };

    issue(0, sb);
    issue(1, sb + STG);

    int cb = 0;                                   // compute buffer = s % 3
    int nb = 2;                                   // next issue buffer = (s+2) % 3
    #pragma unroll 1
    for (int s = 0; s < NST; ++s) {
        if (s + 1 < NST) asm volatile("cp.async.wait_group 1;" ::: "memory");
        else             asm volatile("cp.async.wait_group 0;" ::: "memory");
        __syncthreads();                          // all warps done with buf nb (read at s-1)
        if (s + 2 < NST) issue(s + 2, sb + (uint32_t)nb * STG);

        const uint32_t Abase = sb + (uint32_t)cb * STG;
        const uint32_t Bbase = Abase + 16384u;
        cb = (cb == 2) ? 0 : cb + 1;
        nb = (nb == 2) ? 0 : nb + 1;

        #pragma unroll
        for (int kst = 0; kst < 4; ++kst) {
            uint32_t a[2][4];
            #pragma unroll
            for (int mt = 0; mt < 2; ++mt) {
                int row = warp_m * 32 + mt * 16 + (lane & 15);
                int kc  = kst * 2 + (lane >> 4);
                uint32_t off = (uint32_t)(row * 128 + kc * 16);
                ldsm_x4(Abase + (off ^ (((uint32_t)row & 7u) << 4)),
                        a[mt][0], a[mt][1], a[mt][2], a[mt][3]);
            }
            uint32_t bf[8][2];
            #pragma unroll
            for (int ntp = 0; ntp < 4; ++ntp) {
                int n  = warp_n * 64 + ntp * 16 + ((lane >> 4) << 3) + (lane & 7);
                int kc = kst * 2 + ((lane >> 3) & 1);
                uint32_t off = (uint32_t)(n * 128 + kc * 16);
                ldsm_x4(Bbase + (off ^ (((uint32_t)n & 7u) << 4)),
                        bf[2 * ntp][0], bf[2 * ntp][1],
                        bf[2 * ntp + 1][0], bf[2 * ntp + 1][1]);
            }
            #pragma unroll
            for (int mt = 0; mt < 2; ++mt)
                #pragma unroll
                for (int nt = 0; nt < 8; ++nt)
                    hmma(acc[mt][nt][0], acc[mt][nt][1], acc[mt][nt][2], acc[mt][nt][3],
                         a[mt][0], a[mt][1], a[mt][2], a[mt][3],
                         bf[nt][0], bf[nt][1]);
        }
    }

    // ---- epilogue ----
    const int qm = lane >> 2, qn = (lane & 3) * 2;
    #pragma unroll
    for (int mt = 0; mt < 2; ++mt) {
        #pragma unroll
        for (int nt = 0; nt < 8; ++nt) {
            int oc0 = warp_m * 32 + mt * 16 + qm;
            int px  = warp_n * 64 + nt * 8 + qn;
            float* d0 = out + ((size_t)(b * OC_ + oc0)) * HW_ + (size_t)y * W_ + px;
            *reinterpret_cast<float2*>(d0) =
                make_float2(acc[mt][nt][0], acc[mt][nt][1]);
            *reinterpret_cast<float2*>(d0 + 8 * HW_) =
                make_float2(acc[mt][nt][2], acc[mt][nt][3]);
        }
    }
}

// ---------------------------------------------------------------------------
extern "C" void kernel_launch(void* const* d_in, const int* in_sizes, int n_in,
                              void* d_out, int out_size) {
    const float* content = (const float*)d_in[0];
    const float* style   = (const float*)d_in[1];
    const float* weight  = (const float*)d_in[2];
    const float* mod_w   = (const float*)d_in[3];
    const float* mod_b   = (const float*)d_in[4];
    float* out = (float*)d_out;

    cudaFuncSetAttribute(conv_mma, cudaFuncAttributeMaxDynamicSharedMemorySize, SM_TOTAL);

    mod_kernel<<<512, 128>>>(style, mod_w, mod_b);
    demod_kernel<<<dim3(OC_, B_), 128>>>(weight);
    prep_content<<<dim3(H_, B_), 256>>>(content);
    conv_mma<<<dim3(H_, B_), 256, SM_TOTAL>>>(out);
}

// round 13
// speedup vs baseline: 1.2037x; 1.0152x over previous
#include <cuda_runtime.h>
#include <cuda_fp16.h>
#include <cstdint>

#define B_   16
#define IC_  128
#define OC_  128
#define SD_  512
#define H_   128
#define W_   128
#define HW_  (H_*W_)   // 16384

#define CONV_SCALE 0.029462782549439476f   // 1/sqrt(1152)
#define LIN_SCALE  0.044194173824159216f   // 1/sqrt(512)

// ---------------- device scratch (no allocation allowed) -------------------
__device__ float  g_s[B_ * IC_];                          // modulation s[b][ic]
__device__ __half g_wh[(size_t)B_ * 9 * OC_ * IC_];       // [b][tap][oc][ic] fp16
__device__ __half g_ch[(size_t)B_ * HW_ * IC_];           // [b][pixel][ic] fp16 channels-last

// ---------------- helpers ---------------------------------------------------
__device__ __forceinline__ uint32_t s2u(const void* p) {
    uint32_t a;
    asm("{ .reg .u64 t; cvta.to.shared.u64 t, %1; cvt.u32.u64 %0, t; }" : "=r"(a) : "l"(p));
    return a;
}
__device__ __forceinline__ void cpa16(uint32_t dst, const void* src, int sz) {
    asm volatile("cp.async.cg.shared.global [%0], [%1], 16, %2;"
                 :: "r"(dst), "l"(src), "r"(sz) : "memory");
}
__device__ __forceinline__ void ldsm_x4(uint32_t a, uint32_t& r0, uint32_t& r1,
                                        uint32_t& r2, uint32_t& r3) {
    asm volatile("ldmatrix.sync.aligned.m8n8.x4.shared.b16 {%0,%1,%2,%3}, [%4];"
                 : "=r"(r0), "=r"(r1), "=r"(r2), "=r"(r3) : "r"(a));
}
__device__ __forceinline__ void hmma(float& c0, float& c1, float& c2, float& c3,
                                     uint32_t a0, uint32_t a1, uint32_t a2, uint32_t a3,
                                     uint32_t b0, uint32_t b1) {
    asm volatile(
        "mma.sync.aligned.m16n8k16.row.col.f32.f16.f16.f32 "
        "{%0,%1,%2,%3}, {%4,%5,%6,%7}, {%8,%9}, {%0,%1,%2,%3};"
        : "+f"(c0), "+f"(c1), "+f"(c2), "+f"(c3)
        : "r"(a0), "r"(a1), "r"(a2), "r"(a3), "r"(b0), "r"(b1));
}

// ---------------------------------------------------------------------------
// Kernel 1: s[b][ic] = dot(style[b], mod_w[ic]) * lin_scale + mod_b[ic]
// ---------------------------------------------------------------------------
__global__ void mod_kernel(const float* __restrict__ style,
                           const float* __restrict__ mod_w,
                           const float* __restrict__ mod_b) {
    int warp = threadIdx.x >> 5, lane = threadIdx.x & 31;
    int idx  = blockIdx.x * 4 + warp;
    int b = idx >> 7, ic = idx & 127;
    const float* st = style + b * SD_;
    const float* mw = mod_w + ic * SD_;
    float sum = 0.f;
    #pragma unroll 4
    for (int j = lane; j < SD_; j += 32) sum += st[j] * mw[j];
    #pragma unroll
    for (int o = 16; o; o >>= 1) sum += __shfl_xor_sync(0xffffffffu, sum, o);
    if (lane == 0) g_s[idx] = sum * LIN_SCALE + mod_b[ic];
}

// ---------------------------------------------------------------------------
// Kernel 2: demodulate, write fp16 weights g_wh[b][tap][oc][ic].
// Weights staged through smem (coalesced); ws[ic*9+k] reads conflict-free (9 coprime 32).
// ---------------------------------------------------------------------------
__global__ void demod_kernel(const float* __restrict__ weight) {
    __shared__ float ws[IC_ * 9];
    int oc = blockIdx.x, b = blockIdx.y, ic = threadIdx.x;
    const float* wbase = weight + (size_t)oc * IC_ * 9;
    for (int i = ic; i < IC_ * 9; i += 128) ws[i] = wbase[i];
    float s = g_s[b * IC_ + ic];
    __syncthreads();

    float v[9], ss = 0.f;
    #pragma unroll
    for (int k = 0; k < 9; ++k) { v[k] = CONV_SCALE * ws[ic * 9 + k] * s; ss += v[k] * v[k]; }
    #pragma unroll
    for (int o = 16; o; o >>= 1) ss += __shfl_xor_sync(0xffffffffu, ss, o);
    __shared__ float red[4];
    if ((threadIdx.x & 31) == 0) red[threadIdx.x >> 5] = ss;
    __syncthreads();
    float demod = rsqrtf(red[0] + red[1] + red[2] + red[3] + 1e-8f);
    #pragma unroll
    for (int k = 0; k < 9; ++k)
        g_wh[((size_t)(b * 9 + k) * OC_ + oc) * IC_ + ic] = __float2half(v[k] * demod);
}

// ---------------------------------------------------------------------------
// Kernel 3: content -> fp16 channels-last: g_ch[b][y*W+x][ic] = content[b][ic][y][x]
// float4 reads, uint2 (4-half) packed writes.
// ---------------------------------------------------------------------------
__global__ void prep_content(const float* __restrict__ content) {
    __shared__ __half sm[128][130];
    int y = blockIdx.x, b = blockIdx.y, tid = threadIdx.x;
    const float* src = content + (size_t)b * IC_ * HW_ + y * W_;
    for (int i = tid; i < IC_ * W_ / 4; i += 256) {
        int ic = i >> 5, x0 = (i & 31) * 4;
        float4 v = *reinterpret_cast<const float4*>(src + (size_t)ic * HW_ + x0);
        sm[x0 + 0][ic] = __float2half(v.x);
        sm[x0 + 1][ic] = __float2half(v.y);
        sm[x0 + 2][ic] = __float2half(v.z);
        sm[x0 + 3][ic] = __float2half(v.w);
    }
    __syncthreads();
    uint2* dst = (uint2*)(g_ch + ((size_t)b * HW_ + (size_t)y * W_) * IC_);
    for (int i = tid; i < IC_ * W_ / 4; i += 256) {
        int x = i >> 5, icq = (i & 31) * 4;
        __half2 h0 = __halves2half2(sm[x][icq], sm[x][icq + 1]);
        __half2 h1 = __halves2half2(sm[x][icq + 2], sm[x][icq + 3]);
        uint2 u;
        u.x = *reinterpret_cast<uint32_t*>(&h0);
        u.y = *reinterpret_cast<uint32_t*>(&h1);
        dst[(size_t)x * 32 + (icq >> 2)] = u;
    }
}

// ---------------------------------------------------------------------------
// Kernel 4: implicit GEMM conv (HMMA). CTA = (row y, sample b): D[128 oc][128 px],
// K = 9 taps x 128 ic. 8 warps: warp_m = wid&3 (32 oc), warp_n = wid>>2 (64 px).
// 18 stages (tap x ic-chunk 64): A[128][64] 16KB + B[128][64] 16KB per stage.
// THREE-buffer cp.async ring, ONE __syncthreads per stage, forced 2 CTAs/SM.
// LDSM addressing: addr = base + row*128 + ((in0 + kst*32) ^ swz). in0+96 < 128
// so the XOR (bits 4-6) never carries into the row field -> exact R10 semantics
// with row*128, in0, swz hoisted.
// ---------------------------------------------------------------------------
#define NST 18
#define STG 32768                      // A(16KB) + B(16KB)
#define SM_TOTAL (3 * STG)             // 96KB -> 2 CTAs/SM

__global__ void __launch_bounds__(256, 2) conv_mma(float* __restrict__ out) {
    extern __shared__ char smem[];
    const uint32_t sb = s2u(smem);
    const int tid = threadIdx.x, wid = tid >> 5, lane = tid & 31;
    const int y = blockIdx.x, b = blockIdx.y;
    const int warp_m = wid & 3, warp_n = wid >> 2;

    // hoisted ldsm terms (kst applied inside the XOR at use site)
    uint32_t rowA[2], swA[2], rowB[4], swB[4];
    const uint32_t inA = (uint32_t)(lane >> 4) * 16u;          // 0 or 16
    const uint32_t inB = (uint32_t)((lane >> 3) & 1) * 16u;    // 0 or 16
    #pragma unroll
    for (int mt = 0; mt < 2; ++mt) {
        uint32_t row = warp_m * 32 + mt * 16 + (lane & 15);
        rowA[mt] = row * 128u;
        swA[mt]  = (row & 7u) << 4;
    }
    #pragma unroll
    for (int ntp = 0; ntp < 4; ++ntp) {
        uint32_t n = warp_n * 64 + ntp * 16 + ((lane >> 4) << 3) + (lane & 7);
        rowB[ntp] = 16384u + n * 128u;
        swB[ntp]  = (n & 7u) << 4;
    }

    float acc[2][8][4];
    #pragma unroll
    for (int mt = 0; mt < 2; ++mt)
        #pragma unroll
        for (int nt = 0; nt < 8; ++nt)
            #pragma unroll
            for (int c = 0; c < 4; ++c) acc[mt][nt][c] = 0.f;

    // ---- stage loader into explicit buffer base ----
    auto issue = [&](int s, uint32_t base) {
        const int tap = s % 9, chunk = s / 9;
        const int dy = tap / 3 - 1, dx = tap % 3;
        const char* asrc = (const char*)g_wh
            + ((size_t)(b * 9 + tap) * OC_ * IC_ + chunk * 64) * 2;
        #pragma unroll
        for (int j = 0; j < 4; ++j) {
            int i = tid + j * 256;               // 0..1023
            int row = i >> 3, c16 = i & 7;
            uint32_t off = (uint32_t)(row * 128 + c16 * 16);
            cpa16(base + (off ^ (((uint32_t)row & 7u) << 4)),
                  asrc + (size_t)row * IC_ * 2 + c16 * 16, 16);
        }
        const int yy = y + dy;
        const int rowok = (yy >= 0 && yy < H_);
        const __half* brow = g_ch + ((size_t)b * HW_ + (size_t)(rowok ? yy : 0) * W_) * IC_;
        #pragma unroll
        for (int j = 0; j < 4; ++j) {
            int i = tid + j * 256;
            int row = i >> 3, c16 = i & 7;       // row = x coordinate
            int xs = row + dx - 1;
            int ok = (rowok && xs >= 0 && xs < W_) ? 16 : 0;
            int xc = (xs >= 0 && xs < W_) ? xs : 0;
            uint32_t off = (uint32_t)(row * 128 + c16 * 16);
            cpa16(base + 16384u + (off ^ (((uint32_t)row & 7u) << 4)),
                  (const char*)(brow + (size_t)xc * IC_ + chunk * 64) + c16 * 16, ok);
        }
        asm volatile("cp.async.commit_group;" ::: "memory");
    };

    issue(0, sb);
    issue(1, sb + STG);

    int cb = 0, nb = 2;
    #pragma unroll 1
    for (int s = 0; s < NST; ++s) {
        if (s + 1 < NST) asm volatile("cp.async.wait_group 1;" ::: "memory");
        else             asm volatile("cp.async.wait_group 0;" ::: "memory");
        __syncthreads();
        if (s + 2 < NST) issue(s + 2, sb + (uint32_t)nb * STG);

        const uint32_t base = sb + (uint32_t)cb * STG;
        cb = (cb == 2) ? 0 : cb + 1;
        nb = (nb == 2) ? 0 : nb + 1;

        #pragma unroll
        for (int kst = 0; kst < 4; ++kst) {
            const uint32_t kadd = (uint32_t)kst * 32u;
            uint32_t a[2][4];
            #pragma unroll
            for (int mt = 0; mt < 2; ++mt)
                ldsm_x4(base + rowA[mt] + ((inA + kadd) ^ swA[mt]),
                        a[mt][0], a[mt][1], a[mt][2], a[mt][3]);
            uint32_t bf[8][2];
            #pragma unroll
            for (int ntp = 0; ntp < 4; ++ntp)
                ldsm_x4(base + rowB[ntp] + ((inB + kadd) ^ swB[ntp]),
                        bf[2 * ntp][0], bf[2 * ntp][1],
                        bf[2 * ntp + 1][0], bf[2 * ntp + 1][1]);
            #pragma unroll
            for (int mt = 0; mt < 2; ++mt)
                #pragma unroll
                for (int nt = 0; nt < 8; ++nt)
                    hmma(acc[mt][nt][0], acc[mt][nt][1], acc[mt][nt][2], acc[mt][nt][3],
                         a[mt][0], a[mt][1], a[mt][2], a[mt][3],
                         bf[nt][0], bf[nt][1]);
        }
    }

    // ---- epilogue ----
    const int qm = lane >> 2, qn = (lane & 3) * 2;
    #pragma unroll
    for (int mt = 0; mt < 2; ++mt) {
        #pragma unroll
        for (int nt = 0; nt < 8; ++nt) {
            int oc0 = warp_m * 32 + mt * 16 + qm;
            int px  = warp_n * 64 + nt * 8 + qn;
            float* d0 = out + ((size_t)(b * OC_ + oc0)) * HW_ + (size_t)y * W_ + px;
            *reinterpret_cast<float2*>(d0) =
                make_float2(acc[mt][nt][0], acc[mt][nt][1]);
            *reinterpret_cast<float2*>(d0 + 8 * HW_) =
                make_float2(acc[mt][nt][2], acc[mt][nt][3]);
        }
    }
}

// ---------------------------------------------------------------------------
extern "C" void kernel_launch(void* const* d_in, const int* in_sizes, int n_in,
                              void* d_out, int out_size) {
    const float* content = (const float*)d_in[0];
    const float* style   = (const float*)d_in[1];
    const float* weight  = (const float*)d_in[2];
    const float* mod_w   = (const float*)d_in[3];
    const float* mod_b   = (const float*)d_in[4];
    float* out = (float*)d_out;

    cudaFuncSetAttribute(conv_mma, cudaFuncAttributeMaxDynamicSharedMemorySize, SM_TOTAL);

    mod_kernel<<<512, 128>>>(style, mod_w, mod_b);
    demod_kernel<<<dim3(OC_, B_), 128>>>(weight);
    prep_content<<<dim3(H_, B_), 256>>>(content);
    conv_mma<<<dim3(H_, B_), 256, SM_TOTAL>>>(out);
}